// round 11
// baseline (speedup 1.0000x reference)
#include <cuda_runtime.h>
#include <cuda_fp16.h>
#include <math.h>
#include <stdint.h>

#define NN 8192
#define DD 128
#define NC 256
#define MT 128
#define NT (NN / MT)                      // 64
#define NPAIRS (NT * (NT + 1) / 2)        // 2080
#define KHALF 64
#define MARG 8
#define PARTB 16384                        // 128 rows x 64 halves (128B/row)

typedef unsigned long long u64t;

// ---------------- device globals ----------------
__device__ __half g_hH[NN * DD];
__device__ __half g_hR[NN * DD];
__device__ float g_sq[NN];
__device__ int   g_lab[NN];
__device__ int   g_cnt[NC];
__device__ int   g_is64;
__device__ u64t  g_posP[NN];   // (bits(dist)<<32)|(NN-1-j), atomicMax
__device__ u64t  g_negP[NN];   // (bits(dist)<<32)|j,        atomicMin

#define F_INF __int_as_float(0x7f800000)

// smem: parts 0..3 = Ah Ar Bh Br (16KB each), then control
#define OFF_SQROW  65536
#define OFF_SQCOL  66048
#define OFF_LABROW 66560
#define OFF_LABCOL 67072
#define OFF_ROWP   67584
#define OFF_ROWN   68608
#define OFF_COLP   69632
#define OFF_COLN   70656
#define SMEM_TOTAL 71680

// ---------------- aux kernels ----------------
__global__ void detect_kernel(const int* __restrict__ labw) {
    if (threadIdx.x == 0) {
        int any = 0;
        for (int i = 0; i < 256; i++) any |= labw[2 * i + 1];
        g_is64 = (any == 0) ? 1 : 0;
    }
}

__global__ void convert_labels_kernel(const void* __restrict__ labels) {
    int i = blockIdx.x * blockDim.x + threadIdx.x;
    if (i >= NN) return;
    int v;
    if (g_is64) v = (int)((const long long*)labels)[i];
    else        v = ((const int*)labels)[i];
    g_lab[i] = v;
    g_posP[i] = 0ull;
    g_negP[i] = ~0ull;
    if (i < NC) g_cnt[i] = 0;
}

__global__ void hist_kernel() {
    int i = blockIdx.x * blockDim.x + threadIdx.x;
    if (i < NN) atomicAdd(&g_cnt[g_lab[i] & (NC - 1)], 1);
}

// normalize, sq, fp16 2-way split (h = fp16(x), r = fp16(x - h))
__global__ void normalize_split_kernel(const float* __restrict__ x) {
    int row = blockIdx.x;
    int t = threadIdx.x;
    float v = x[row * DD + t];
    float s = v * v;
    #pragma unroll
    for (int o = 16; o > 0; o >>= 1) s += __shfl_xor_sync(0xffffffffu, s, o);
    __shared__ float ws[4];
    __shared__ float ws2[4];
    int warp = t >> 5, lane = t & 31;
    if (lane == 0) ws[warp] = s;
    __syncthreads();
    float tot = ws[0] + ws[1] + ws[2] + ws[3];
    float nrm = __fsqrt_rn(tot);
    float xn  = __fdiv_rn(v, nrm);
    float s2 = xn * xn;
    #pragma unroll
    for (int o = 16; o > 0; o >>= 1) s2 += __shfl_xor_sync(0xffffffffu, s2, o);
    if (lane == 0) ws2[warp] = s2;
    __syncthreads();
    if (t == 0) g_sq[row] = ws2[0] + ws2[1] + ws2[2] + ws2[3];

    __half h = __float2half_rn(xn);
    float r1 = xn - __half2float(h);
    g_hH[row * DD + t] = h;
    g_hR[row * DD + t] = __float2half_rn(r1);
}

// ---------------- guarded exact-order compares (dist semantics on d2) ----------------
// "new beats cur" for argmax-dist / argmin-dist with first-index tie rule.
__device__ __forceinline__ bool gtPos(int bN, int iN, int bC, int iC) {
    if (bN == bC) return iN < iC;
    if (bN > bC + MARG) return true;
    if (bN + MARG < bC) return false;
    float dn = __fsqrt_rn(__int_as_float(bN));
    float dc = __fsqrt_rn(__int_as_float(bC));
    if (dn != dc) return dn > dc;
    return iN < iC;
}
__device__ __forceinline__ bool ltNeg(int bN, int iN, int bC, int iC) {
    if (bN == bC) return iN < iC;
    if (bN + MARG < bC) return true;
    if (bN > bC + MARG) return false;
    float dn = __fsqrt_rn(__int_as_float(bN));
    float dc = __fsqrt_rn(__int_as_float(bC));
    if (dn != dc) return dn < dc;
    return iN < iC;
}

// ---------------- HMMA miner ----------------
extern __shared__ __align__(128) char dynsmem[];

__global__ void __launch_bounds__(256, 2) mine_kernel() {
    // triangular pair decode
    int t = blockIdx.x, I = 0;
    while (t >= NT - I) { t -= NT - I; I++; }
    const int J = I + t;
    const int rowBase = I * MT, colBase = J * MT;
    const bool offdiag = (I != J);

    char* smem = dynsmem;
    float* sSqRow = (float*)(smem + OFF_SQROW);
    float* sSqCol = (float*)(smem + OFF_SQCOL);
    int*   sLabRow = (int*)(smem + OFF_LABROW);
    int*   sLabCol = (int*)(smem + OFF_LABCOL);
    u64t*  sRowP = (u64t*)(smem + OFF_ROWP);
    u64t*  sRowN = (u64t*)(smem + OFF_ROWN);
    u64t*  sColP = (u64t*)(smem + OFF_COLP);
    u64t*  sColN = (u64t*)(smem + OFF_COLN);

    const int tid = threadIdx.x, wid = tid >> 5, lane = tid & 31;
    const int g = lane >> 2, tig = lane & 3;
    const int warpRow = wid >> 2, warpCol = wid & 3;   // 2x4 warp grid, 64x32 tiles

    if (tid < MT) {
        sSqRow[tid]  = g_sq[rowBase + tid];
        sLabRow[tid] = g_lab[rowBase + tid];
        sRowP[tid] = 0ull;  sRowN[tid] = ~0ull;
    } else {
        int u = tid - MT;
        sSqCol[u]  = g_sq[colBase + u];
        sLabCol[u] = g_lab[colBase + u];
        sColP[u] = 0ull;  sColN[u] = ~0ull;
    }

    float acc[4][4][4];
    #pragma unroll
    for (int a = 0; a < 4; a++)
        #pragma unroll
        for (int b = 0; b < 4; b++)
            #pragma unroll
            for (int c = 0; c < 4; c++) acc[a][b][c] = 0.0f;

    const __half* srcs[4] = {g_hH + (size_t)rowBase * DD, g_hR + (size_t)rowBase * DD,
                             g_hH + (size_t)colBase * DD, g_hR + (size_t)colBase * DD};

    for (int stage = 0; stage < 2; ++stage) {
        __syncthreads();   // previous stage's mma done with smem
        // fill 4 parts: 16B chunks, XOR-swizzled rows (conflict-free LDS/STS)
        for (int c = tid; c < 4096; c += 256) {
            int part = c >> 10, rem = c & 1023, row = rem >> 3, ch = rem & 7;
            const __half* src = srcs[part] + (size_t)row * DD + stage * KHALF + ch * 8;
            uint4 v = *(const uint4*)src;
            uint32_t off = part * PARTB + row * 128 + ((ch * 16) ^ ((row & 7) << 4));
            *(uint4*)(smem + off) = v;
        }
        __syncthreads();

        const int paP[3] = {0, 0, 1}, pbP[3] = {2, 3, 2};   // hh, hr, rh
        #pragma unroll
        for (int prod = 0; prod < 3; ++prod) {
            const uint32_t aBase = paP[prod] * PARTB;
            const uint32_t bBase = pbP[prod] * PARTB;
            #pragma unroll
            for (int ks = 0; ks < 4; ++ks) {
                const uint32_t bo0 = ks * 32 + tig * 4, bo1 = bo0 + 16;
                uint32_t af[4][4], bf[4][2];
                #pragma unroll
                for (int mr = 0; mr < 4; mr++) {
                    int r0 = warpRow * 64 + mr * 16 + g, r1 = r0 + 8;
                    uint32_t sw0 = (r0 & 7) << 4;
                    af[mr][0] = *(const uint32_t*)(smem + aBase + r0 * 128 + (bo0 ^ sw0));
                    af[mr][1] = *(const uint32_t*)(smem + aBase + r1 * 128 + (bo0 ^ sw0));
                    af[mr][2] = *(const uint32_t*)(smem + aBase + r0 * 128 + (bo1 ^ sw0));
                    af[mr][3] = *(const uint32_t*)(smem + aBase + r1 * 128 + (bo1 ^ sw0));
                }
                #pragma unroll
                for (int mc = 0; mc < 4; mc++) {
                    int n = warpCol * 32 + mc * 8 + g;
                    uint32_t sw = (n & 7) << 4;
                    bf[mc][0] = *(const uint32_t*)(smem + bBase + n * 128 + (bo0 ^ sw));
                    bf[mc][1] = *(const uint32_t*)(smem + bBase + n * 128 + (bo1 ^ sw));
                }
                #pragma unroll
                for (int mr = 0; mr < 4; mr++)
                    #pragma unroll
                    for (int mc = 0; mc < 4; mc++)
                        asm volatile(
                            "mma.sync.aligned.m16n8k16.row.col.f32.f16.f16.f32 "
                            "{%0,%1,%2,%3}, {%4,%5,%6,%7}, {%8,%9}, {%0,%1,%2,%3};"
                            : "+f"(acc[mr][mc][0]), "+f"(acc[mr][mc][1]),
                              "+f"(acc[mr][mc][2]), "+f"(acc[mr][mc][3])
                            : "r"(af[mr][0]), "r"(af[mr][1]), "r"(af[mr][2]), "r"(af[mr][3]),
                              "r"(bf[mc][0]), "r"(bf[mc][1]));
            }
        }
    }

    // ---------------- epilogue ----------------
    // acc element mapping (m16n8k16): c0:(g, tig*2) c1:(g, tig*2+1)
    //                                 c2:(g+8, tig*2) c3:(g+8, tig*2+1)
    int rloc[8], cloc[8], labR[8], labC[8];
    float sqR[8], sqC[8];
    #pragma unroll
    for (int mr = 0; mr < 4; mr++)
        #pragma unroll
        for (int sub = 0; sub < 2; sub++) {
            int s = mr * 2 + sub;
            rloc[s] = warpRow * 64 + mr * 16 + g + sub * 8;
            sqR[s] = sSqRow[rloc[s]];  labR[s] = sLabRow[rloc[s]];
        }
    #pragma unroll
    for (int mc = 0; mc < 4; mc++)
        #pragma unroll
        for (int q = 0; q < 2; q++) {
            int s = mc * 2 + q;
            cloc[s] = warpCol * 32 + mc * 8 + tig * 2 + q;
            sqC[s] = sSqCol[cloc[s]];  labC[s] = sLabCol[cloc[s]];
        }

    int rPb[8], rPi[8], rNb[8], rNi[8], cPb[8], cPi[8], cNb[8], cNi[8];
    #pragma unroll
    for (int s = 0; s < 8; s++) {
        rPb[s] = (int)0xFF800000u; rPi[s] = 0x7FFFFFFF;
        rNb[s] = 0x7F800000;       rNi[s] = 0x7FFFFFFF;
        cPb[s] = (int)0xFF800000u; cPi[s] = 0x7FFFFFFF;
        cNb[s] = 0x7F800000;       cNi[s] = 0x7FFFFFFF;
    }

    #pragma unroll
    for (int mr = 0; mr < 4; mr++)
        #pragma unroll
        for (int sub = 0; sub < 2; sub++) {
            const int rs = mr * 2 + sub;
            const int i = rowBase + rloc[rs];
            #pragma unroll
            for (int mc = 0; mc < 4; mc++)
                #pragma unroll
                for (int q = 0; q < 2; q++) {
                    const int cs = mc * 2 + q;
                    const int j = colBase + cloc[cs];
                    float dot = acc[mr][mc][sub * 2 + q];
                    float d2 = fmaxf(fmaf(-2.0f, dot, sqR[rs] + sqC[cs]), 0.0f);
                    const bool same = (labR[rs] == labC[cs]);
                    int bp = (same && (i != j)) ? __float_as_int(d2) : 0;
                    int bn = same ? 0x7F800000 : __float_as_int(d2);
                    if (gtPos(bp, j, rPb[rs], rPi[rs])) { rPb[rs] = bp; rPi[rs] = j; }
                    if (ltNeg(bn, j, rNb[rs], rNi[rs])) { rNb[rs] = bn; rNi[rs] = j; }
                    if (gtPos(bp, i, cPb[cs], cPi[cs])) { cPb[cs] = bp; cPi[cs] = i; }
                    if (ltNeg(bn, i, cNb[cs], cNi[cs])) { cNb[cs] = bn; cNi[cs] = i; }
                }
        }

    // row-side: merge across the 4 lanes sharing each row (width-4 tree)
    #pragma unroll
    for (int s = 0; s < 8; s++) {
        #pragma unroll
        for (int d = 1; d < 4; d <<= 1) {
            int ob = __shfl_down_sync(0xffffffffu, rPb[s], d, 4);
            int oi = __shfl_down_sync(0xffffffffu, rPi[s], d, 4);
            if (gtPos(ob, oi, rPb[s], rPi[s])) { rPb[s] = ob; rPi[s] = oi; }
            ob = __shfl_down_sync(0xffffffffu, rNb[s], d, 4);
            oi = __shfl_down_sync(0xffffffffu, rNi[s], d, 4);
            if (ltNeg(ob, oi, rNb[s], rNi[s])) { rNb[s] = ob; rNi[s] = oi; }
        }
        // col-side: lanes sharing a col are stride-4 apart
        #pragma unroll
        for (int d = 4; d < 32; d <<= 1) {
            int ob = __shfl_down_sync(0xffffffffu, cPb[s], d, 32);
            int oi = __shfl_down_sync(0xffffffffu, cPi[s], d, 32);
            if (gtPos(ob, oi, cPb[s], cPi[s])) { cPb[s] = ob; cPi[s] = oi; }
            ob = __shfl_down_sync(0xffffffffu, cNb[s], d, 32);
            oi = __shfl_down_sync(0xffffffffu, cNi[s], d, 32);
            if (ltNeg(ob, oi, cNb[s], cNi[s])) { cNb[s] = ob; cNi[s] = oi; }
        }
    }

    // finalists -> dist domain, packed u64, smem atomic merge
    if (tig == 0) {
        #pragma unroll
        for (int s = 0; s < 8; s++) {
            float pd = __fsqrt_rn(__int_as_float(rPb[s]));
            float nd = __fsqrt_rn(__int_as_float(rNb[s]));
            u64t kp = ((u64t)__float_as_uint(pd) << 32) | (u64t)(NN - 1 - rPi[s]);
            u64t kn = ((u64t)__float_as_uint(nd) << 32) | (u64t)rNi[s];
            atomicMax(&sRowP[rloc[s]], kp);
            atomicMin(&sRowN[rloc[s]], kn);
        }
    }
    if (g == 0) {
        #pragma unroll
        for (int s = 0; s < 8; s++) {
            float pd = __fsqrt_rn(__int_as_float(cPb[s]));
            float nd = __fsqrt_rn(__int_as_float(cNb[s]));
            u64t kp = ((u64t)__float_as_uint(pd) << 32) | (u64t)(NN - 1 - cPi[s]);
            u64t kn = ((u64t)__float_as_uint(nd) << 32) | (u64t)cNi[s];
            atomicMax(&sColP[cloc[s]], kp);
            atomicMin(&sColN[cloc[s]], kn);
        }
    }
    __syncthreads();
    if (tid < MT) {
        atomicMax(&g_posP[rowBase + tid], sRowP[tid]);
        atomicMin(&g_negP[rowBase + tid], sRowN[tid]);
        if (offdiag) {
            atomicMax(&g_posP[colBase + tid], sColP[tid]);
            atomicMin(&g_negP[colBase + tid], sColN[tid]);
        }
    }
}

// Outputs as FLOAT32 (harness normalizes reference int/bool to float32)
__global__ void final_kernel(float* __restrict__ out) {
    int i = blockIdx.x * blockDim.x + threadIdx.x;
    if (i >= NN) return;
    const int bpi = NN - 1 - (int)(g_posP[i] & 0xffffffffu);
    const int bni = (int)(g_negP[i] & 0xffffffffu);
    const int c = g_cnt[g_lab[i] & (NC - 1)];
    const float keep = (c >= 2 && c < NN) ? 1.0f : 0.0f;
    out[0 * NN + i] = (float)i;
    out[1 * NN + i] = (float)bpi;
    out[2 * NN + i] = (float)bni;
    out[3 * NN + i] = keep;
}

extern "C" void kernel_launch(void* const* d_in, const int* in_sizes, int n_in,
                              void* d_out, int out_size) {
    const float* embeds = (const float*)d_in[0];
    const void*  labels = d_in[1];
    float* out = (float*)d_out;

    cudaFuncSetAttribute(mine_kernel,
                         cudaFuncAttributeMaxDynamicSharedMemorySize, SMEM_TOTAL);

    detect_kernel<<<1, 32>>>((const int*)labels);
    convert_labels_kernel<<<(NN + 255) / 256, 256>>>(labels);
    hist_kernel<<<(NN + 255) / 256, 256>>>();
    normalize_split_kernel<<<NN, DD>>>(embeds);
    mine_kernel<<<NPAIRS, 256, SMEM_TOTAL>>>();
    final_kernel<<<(NN + 255) / 256, 256>>>(out);
}